// round 6
// baseline (speedup 1.0000x reference)
#include <cuda_runtime.h>

#define F_IN   10000
#define F_PAD  10240     // padded to 80 groups of 128 columns
#define NROWS  4096
#define GROUPS 80        // column groups of 128
#define C      4         // 32-col chunks per lane
#define WARPS  4         // warps per block (one group each)
#define RB     64        // rows per block
#define NPART  (GROUPS * 8)          // 640 partials per row
#define L2E    1.4426950408889634f
#define LN2    0.6931471805599453f
#define HL2PI2 1.3257480647361593f   // 0.5*log2(2*pi)

// scratch (no allocations allowed)
__device__ float g_pp[F_PAD * 9];               // per-column [m][{-K, B, C_}] base-2 Horner params
__device__ float g_part[(size_t)NROWS * NPART]; // per-row partials, row-major

__device__ __forceinline__ float ex2(float x) {
    float r; asm("ex2.approx.ftz.f32 %0, %1;" : "=f"(r) : "f"(x)); return r;
}
__device__ __forceinline__ float lg2(float x) {
    float r; asm("lg2.approx.ftz.f32 %0, %1;" : "=f"(r) : "f"(x)); return r;
}

// Kernel 1: one thread per (f, m) — 3x the parallelism of per-f, shorter
// dependent-load chains. Folds w1 log-softmax, log(std), permutation into
// per-column base-2 Horner constants: t_m(x) = (-K x + B) x + C_.
// Pad columns contribute exactly 0: t0 = 0, t1 = t2 = -1e30.
__global__ void prep_kernel(const float* __restrict__ means,
                            const float* __restrict__ stds,
                            const float* __restrict__ w1,
                            const int*   __restrict__ idx) {
    int t = blockIdx.x * blockDim.x + threadIdx.x;
    int f = t / 3, m = t - f * 3;
    if (f >= F_PAD) return;
    if (f >= F_IN) {
        if (m == 0) {
            float* q = &g_pp[(size_t)f * 9];
            q[0]=0.f; q[1]=0.f; q[2]=0.f;
            q[3]=0.f; q[4]=0.f; q[5]=-1e30f;
            q[6]=0.f; q[7]=0.f; q[8]=-1e30f;
        }
        return;
    }
    float u0 = w1[f*3+0]*L2E, u1 = w1[f*3+1]*L2E, u2 = w1[f*3+2]*L2E;
    float mu = fmaxf(u0, fmaxf(u1, u2));
    float l2 = mu + lg2(ex2(u0-mu) + ex2(u1-mu) + ex2(u2-mu));  // log2 softmax denom
    float um   = (m == 0) ? u0 : (m == 1 ? u1 : u2);
    float mean = means[f*3+m];
    float sd   = stds[f*3+m];
    float K    = 0.7213475204444817f / (sd * sd);   // 0.5*log2(e)/sd^2
    float A    = (um - l2) - lg2(sd) - HL2PI2;
    float* q = &g_pp[(size_t)idx[f] * 9 + m * 3];
    q[0] = -K;
    q[1] = 2.0f * K * mean;
    q[2] = A - K * mean * mean;
}

// Kernel 2: warp owns 128 columns (lane = column), params in registers for the
// whole row sweep, coalesced streaming LDG of x with a 2-row-deep software
// pipeline (8 LDGs in flight per lane-pair of rows). Per row: per-lane
// (a = sum of mx, p = prod of (1+s)); 2-step butterfly (add a / mul p),
// ONE lg2, lanes 0-7 store 8 partials.
__global__ __launch_bounds__(WARPS * 32) void spn_main(const float* __restrict__ x) {
    const int lane = threadIdx.x & 31;
    const int w    = threadIdx.x >> 5;
    const int g    = blockIdx.x * WARPS + w;      // column group 0..79
    const int r0   = blockIdx.y * RB;
    const int cbase = g * 128 + lane;

    float nk[C][3], pb[C][3], pc[C][3];
    #pragma unroll
    for (int c = 0; c < C; c++) {
        const float* p = &g_pp[(size_t)(cbase + c * 32) * 9];
        #pragma unroll
        for (int m = 0; m < 3; m++) {
            nk[c][m] = __ldg(p + m*3 + 0);
            pb[c][m] = __ldg(p + m*3 + 1);
            pc[c][m] = __ldg(p + m*3 + 2);
        }
    }
    bool inb[C];
    #pragma unroll
    for (int c = 0; c < C; c++) inb[c] = (cbase + c * 32) < F_IN;

    const float* xbase = x + (size_t)r0 * F_IN + g * 128 + lane;

    auto body = [&](int rval, const float (&xval)[C]) {
        float a = 0.0f, p = 1.0f;
        #pragma unroll
        for (int c = 0; c < C; c++) {
            float xv = xval[c];
            float t0 = fmaf(fmaf(xv, nk[c][0], pb[c][0]), xv, pc[c][0]);
            float t1 = fmaf(fmaf(xv, nk[c][1], pb[c][1]), xv, pc[c][1]);
            float t2 = fmaf(fmaf(xv, nk[c][2], pb[c][2]), xv, pc[c][2]);
            float hi = fmaxf(t0, t1), lo = fminf(t0, t1);
            float mx = fmaxf(hi, t2), md = fminf(hi, t2);
            float s  = ex2(md - mx) + ex2(lo - mx);
            a += mx;
            p = fmaf(s, p, p);     // p *= (1 + s)
        }
        a += __shfl_xor_sync(0xffffffffu, a, 16);
        p *= __shfl_xor_sync(0xffffffffu, p, 16);
        a += __shfl_xor_sync(0xffffffffu, a, 8);
        p *= __shfl_xor_sync(0xffffffffu, p, 8);
        float v = a + lg2(p);
        if (lane < 8)
            g_part[(size_t)(r0 + rval) * NPART + g * 8 + lane] = v;
    };

    // 2-row-deep pipeline: buf holds rows r, r+1; while computing them the
    // loads for rows r+2, r+3 are in flight.
    float buf0[C], buf1[C];
    #pragma unroll
    for (int c = 0; c < C; c++) {
        buf0[c] = inb[c] ? __ldcs(xbase + c * 32) : 0.0f;
        buf1[c] = inb[c] ? __ldcs(xbase + (size_t)F_IN + c * 32) : 0.0f;
    }

    for (int r = 0; r + 2 < RB; r += 2) {
        float cur0[C], cur1[C];
        #pragma unroll
        for (int c = 0; c < C; c++) { cur0[c] = buf0[c]; cur1[c] = buf1[c]; }
        const float* xq0 = xbase + (size_t)(r + 2) * F_IN;
        const float* xq1 = xbase + (size_t)(r + 3) * F_IN;
        #pragma unroll
        for (int c = 0; c < C; c++) {
            buf0[c] = inb[c] ? __ldcs(xq0 + c * 32) : 0.0f;
            buf1[c] = inb[c] ? __ldcs(xq1 + c * 32) : 0.0f;
        }
        body(r, cur0);
        body(r + 1, cur1);
    }
    body(RB - 2, buf0);
    body(RB - 1, buf1);
}

// Kernel 3: fold 640 partials per row (one warp per row, deterministic order).
__global__ void reduce_kernel(float* __restrict__ out) {
    const int lane = threadIdx.x & 31;
    const int n    = blockIdx.x * (blockDim.x >> 5) + (threadIdx.x >> 5);
    if (n >= NROWS) return;
    const float* p = &g_part[(size_t)n * NPART];
    float s = 0.0f;
    #pragma unroll
    for (int i = 0; i < NPART / 32; i++) s += p[lane + i * 32];
    #pragma unroll
    for (int off = 16; off; off >>= 1)
        s += __shfl_xor_sync(0xffffffffu, s, off);
    if (lane == 0) out[n] = s * LN2;
}

extern "C" void kernel_launch(void* const* d_in, const int* in_sizes, int n_in,
                              void* d_out, int out_size) {
    const float* x     = (const float*)d_in[0];
    const float* means = (const float*)d_in[1];
    const float* stds  = (const float*)d_in[2];
    const float* w1    = (const float*)d_in[3];
    // d_in[4..7] = w2..w5: provably no-ops (log_softmax over size-1 axis == 0)
    const int*   idx   = (const int*)d_in[8];

    prep_kernel<<<(F_PAD * 3 + 127) / 128, 128>>>(means, stds, w1, idx);
    spn_main<<<dim3(GROUPS / WARPS, NROWS / RB), WARPS * 32>>>(x);
    reduce_kernel<<<NROWS / 8, 256>>>((float*)d_out);
}

// round 7
// speedup vs baseline: 1.0341x; 1.0341x over previous
#include <cuda_runtime.h>

#define F_IN   10000
#define F_PAD  10240     // padded to 80 groups of 128 columns
#define NROWS  4096
#define GROUPS 80        // column groups of 128
#define WARPS  4         // warps per block (one group each)
#define RB     64        // rows per block
#define NPART  (GROUPS * 8)          // 640 partials per row
#define L2E    1.4426950408889634f
#define LN2    0.6931471805599453f
#define HL2PI2 1.3257480647361593f   // 0.5*log2(2*pi)

// scratch (no allocations allowed)
__device__ float g_pp[F_PAD * 9];               // per-column [m][{-K, B, C_}] base-2 Horner params
__device__ float g_part[(size_t)NROWS * NPART]; // per-row partials, row-major

__device__ __forceinline__ float ex2(float x) {
    float r; asm("ex2.approx.ftz.f32 %0, %1;" : "=f"(r) : "f"(x)); return r;
}
__device__ __forceinline__ float lg2(float x) {
    float r; asm("lg2.approx.ftz.f32 %0, %1;" : "=f"(r) : "f"(x)); return r;
}

// Kernel 1: one thread per (f, m). Folds w1 log-softmax, log(std), permutation
// into per-column base-2 Horner constants: t_m(x) = (-K x + B) x + C_.
// Pad columns contribute exactly 0: t0 = 0, t1 = t2 = -1e30.
__global__ void prep_kernel(const float* __restrict__ means,
                            const float* __restrict__ stds,
                            const float* __restrict__ w1,
                            const int*   __restrict__ idx) {
    int t = blockIdx.x * blockDim.x + threadIdx.x;
    int f = t / 3, m = t - f * 3;
    if (f >= F_PAD) return;
    if (f >= F_IN) {
        if (m == 0) {
            float* q = &g_pp[(size_t)f * 9];
            q[0]=0.f; q[1]=0.f; q[2]=0.f;
            q[3]=0.f; q[4]=0.f; q[5]=-1e30f;
            q[6]=0.f; q[7]=0.f; q[8]=-1e30f;
        }
        return;
    }
    float u0 = w1[f*3+0]*L2E, u1 = w1[f*3+1]*L2E, u2 = w1[f*3+2]*L2E;
    float mu = fmaxf(u0, fmaxf(u1, u2));
    float l2 = mu + lg2(ex2(u0-mu) + ex2(u1-mu) + ex2(u2-mu));  // log2 softmax denom
    float um   = (m == 0) ? u0 : (m == 1 ? u1 : u2);
    float mean = means[f*3+m];
    float sd   = stds[f*3+m];
    float K    = 0.7213475204444817f / (sd * sd);   // 0.5*log2(e)/sd^2
    float A    = (um - l2) - lg2(sd) - HL2PI2;
    float* q = &g_pp[(size_t)idx[f] * 9 + m * 3];
    q[0] = -K;
    q[1] = 2.0f * K * mean;
    q[2] = A - K * mean * mean;
}

// Kernel 2: warp owns 128 consecutive columns; lane owns 4 CONSECUTIVE columns
// -> ONE float4 LDG per row per lane (perfectly coalesced 512B per warp).
// Params in registers for the whole 64-row sweep; 1-row software prefetch
// (R5 structure — 2-deep regressed). Per row: per-lane (a = sum mx,
// p = prod(1+s)); 2-step butterfly, ONE lg2, lanes 0-7 store 8 partials.
__global__ __launch_bounds__(WARPS * 32) void spn_main(const float* __restrict__ x) {
    const int lane = threadIdx.x & 31;
    const int w    = threadIdx.x >> 5;
    const int g    = blockIdx.x * WARPS + w;      // column group 0..79
    const int r0   = blockIdx.y * RB;
    const int cbase = g * 128 + lane * 4;         // 4 consecutive columns

    float nk[4][3], pb[4][3], pc[4][3];
    #pragma unroll
    for (int c = 0; c < 4; c++) {
        const float* p = &g_pp[(size_t)(cbase + c) * 9];
        #pragma unroll
        for (int m = 0; m < 3; m++) {
            nk[c][m] = __ldg(p + m*3 + 0);
            pb[c][m] = __ldg(p + m*3 + 1);
            pc[c][m] = __ldg(p + m*3 + 2);
        }
    }
    // 10000 % 4 == 0 -> a lane's float4 is entirely in- or out-of-bounds.
    const bool inb = cbase < F_IN;

    const float4* xb = (const float4*)(x + (size_t)r0 * F_IN + g * 128) + lane;
    const int rstride = F_IN / 4;   // row stride in float4 units

    auto body = [&](int rval, float4 xv4) {
        const float xa[4] = {xv4.x, xv4.y, xv4.z, xv4.w};
        float a = 0.0f, p = 1.0f;
        #pragma unroll
        for (int c = 0; c < 4; c++) {
            float xv = xa[c];
            float t0 = fmaf(fmaf(xv, nk[c][0], pb[c][0]), xv, pc[c][0]);
            float t1 = fmaf(fmaf(xv, nk[c][1], pb[c][1]), xv, pc[c][1]);
            float t2 = fmaf(fmaf(xv, nk[c][2], pb[c][2]), xv, pc[c][2]);
            float hi = fmaxf(t0, t1), lo = fminf(t0, t1);
            float mx = fmaxf(hi, t2), md = fminf(hi, t2);
            float s  = ex2(md - mx) + ex2(lo - mx);
            a += mx;
            p = fmaf(s, p, p);     // p *= (1 + s)
        }
        a += __shfl_xor_sync(0xffffffffu, a, 16);
        p *= __shfl_xor_sync(0xffffffffu, p, 16);
        a += __shfl_xor_sync(0xffffffffu, a, 8);
        p *= __shfl_xor_sync(0xffffffffu, p, 8);
        float v = a + lg2(p);
        if (lane < 8)
            g_part[(size_t)(r0 + rval) * NPART + g * 8 + lane] = v;
    };

    const float4 zero4 = make_float4(0.f, 0.f, 0.f, 0.f);
    float4 nxt = inb ? __ldcs(xb) : zero4;

    #pragma unroll 2
    for (int r = 0; r < RB - 1; r++) {
        float4 cur = nxt;
        nxt = inb ? __ldcs(xb + (size_t)(r + 1) * rstride) : zero4;
        body(r, cur);
    }
    body(RB - 1, nxt);
}

// Kernel 3: fold 640 partials per row (one warp per row, deterministic order).
__global__ void reduce_kernel(float* __restrict__ out) {
    const int lane = threadIdx.x & 31;
    const int n    = blockIdx.x * (blockDim.x >> 5) + (threadIdx.x >> 5);
    if (n >= NROWS) return;
    const float* p = &g_part[(size_t)n * NPART];
    float s = 0.0f;
    #pragma unroll
    for (int i = 0; i < NPART / 32; i++) s += p[lane + i * 32];
    #pragma unroll
    for (int off = 16; off; off >>= 1)
        s += __shfl_xor_sync(0xffffffffu, s, off);
    if (lane == 0) out[n] = s * LN2;
}

extern "C" void kernel_launch(void* const* d_in, const int* in_sizes, int n_in,
                              void* d_out, int out_size) {
    const float* x     = (const float*)d_in[0];
    const float* means = (const float*)d_in[1];
    const float* stds  = (const float*)d_in[2];
    const float* w1    = (const float*)d_in[3];
    // d_in[4..7] = w2..w5: provably no-ops (log_softmax over size-1 axis == 0)
    const int*   idx   = (const int*)d_in[8];

    prep_kernel<<<(F_PAD * 3 + 127) / 128, 128>>>(means, stds, w1, idx);
    spn_main<<<dim3(GROUPS / WARPS, NROWS / RB), WARPS * 32>>>(x);
    reduce_kernel<<<NROWS / 8, 256>>>((float*)d_out);
}